// round 16
// baseline (speedup 1.0000x reference)
#include <cuda_runtime.h>
#include <cuda_pipeline.h>
#include <cuda_bf16.h>
#include <cstdint>
#include <float.h>

#define Bg   64
#define Lg   1024
#define Kn   16
#define Ntot (Bg * Lg)

// ---- scratch (static device globals; zero-initialized; no allocation) ----
__device__ float g_s[Ntot * 4];             //  1 MB  learned kNN space
__device__ float g_h[Ntot * 64];            // 16 MB  propagated features (fp32)
__device__ __nv_bfloat16 g_xhi[Ntot * 128]; // 16 MB  x split hi   [node][k]
__device__ __nv_bfloat16 g_xlo[Ntot * 128]; // 16 MB  x split lo
__device__ __nv_bfloat16 g_ahi[Ntot * 128]; // 16 MB  agg split hi [node][mean|max]
__device__ __nv_bfloat16 g_alo[Ntot * 128]; // 16 MB  agg split lo
__device__ __nv_bfloat16 g_Bhi[128 * 256];  // W_out^T hi  [n][k=256]
__device__ __nv_bfloat16 g_Blo[128 * 256];  // W_out^T lo
__device__ __nv_bfloat16 g_Ehi[96 * 128];   // W_comb^T hi [n=96(pad)][k=128]
__device__ __nv_bfloat16 g_Elo[96 * 128];   // W_comb^T lo (rows 72..95 stay zero)

__device__ __forceinline__ uint32_t smem_u32(const void* p) {
    uint32_t a;
    asm("{ .reg .u64 t; cvta.to.shared.u64 t, %1; cvt.u32.u64 %0, t; }"
        : "=r"(a) : "l"(p));
    return a;
}

#define LDSM_X4(r0, r1, r2, r3, addr) \
    asm volatile("ldmatrix.sync.aligned.m8n8.x4.shared.b16 {%0,%1,%2,%3}, [%4];" \
                 : "=r"(r0), "=r"(r1), "=r"(r2), "=r"(r3) : "r"(addr))

#define MMA16816(c, a, b) \
    asm volatile("mma.sync.aligned.m16n8k16.row.col.f32.bf16.bf16.f32 " \
                 "{%0,%1,%2,%3}, {%4,%5,%6,%7}, {%8,%9}, {%0,%1,%2,%3};" \
                 : "+f"((c)[0]), "+f"((c)[1]), "+f"((c)[2]), "+f"((c)[3]) \
                 : "r"((a)[0]), "r"((a)[1]), "r"((a)[2]), "r"((a)[3]), \
                   "r"((b)[0]), "r"((b)[1]))

__device__ __forceinline__ unsigned pack_bf2(__nv_bfloat16 a, __nv_bfloat16 b) {
    __nv_bfloat162 p = __halves2bfloat162(a, b);
    return *reinterpret_cast<unsigned*>(&p);
}
__device__ __forceinline__ void split_bf(float v, __nv_bfloat16& h, __nv_bfloat16& l) {
    h = __float2bfloat16_rn(v);
    l = __float2bfloat16_rn(v - __bfloat162float(h));
}

// ============================================================
// Kernel 0: weight prep (R8 proven).
// ============================================================
__global__ __launch_bounds__(512) void k_wcvt(
    const float* __restrict__ Wout,
    const float* __restrict__ Ws, const float* __restrict__ Wh)
{
    int idx = blockIdx.x * 512 + threadIdx.x;      // 0..32767
    {
        int n = idx & 127, k = idx >> 7;
        float w = Wout[(size_t)k * 128 + n];
        __nv_bfloat16 h, l;
        split_bf(w, h, l);
        g_Bhi[n * 256 + k] = h;
        g_Blo[n * 256 + k] = l;
    }
    if (idx < 72 * 128) {
        int n = idx >> 7, k = idx & 127;
        float w = (n < 64) ? Wh[k * 64 + n] : Ws[k * 4 + (n - 64)];
        __nv_bfloat16 h, l;
        split_bf(w, h, l);
        g_Ehi[n * 128 + k] = h;
        g_Elo[n * 128 + k] = l;
    }
}

// ============================================================
// Kernel 1: fused s/h embedding via HMMA split-bf16 (R10 proven).
// ============================================================
#define EP 72

__global__ __launch_bounds__(256) void k_embed(
    const float* __restrict__ x,
    const float* __restrict__ bs, const float* __restrict__ bh)
{
    __shared__ __nv_bfloat16 Ah[64][EP];
    __shared__ __nv_bfloat16 Al[64][EP];
    __shared__ __nv_bfloat16 Bh[96][EP];
    __shared__ __nv_bfloat16 Bl[96][EP];

    int t = threadIdx.x;
    int wid = t >> 5, lane = t & 31;
    int warp_m = wid & 3;
    int warp_n = wid >> 2;
    int brow = blockIdx.x * 64;

    float acc[5][4];
#pragma unroll
    for (int ni = 0; ni < 5; ni++)
#pragma unroll
        for (int r = 0; r < 4; r++) acc[ni][r] = 0.f;

    int lg = lane >> 3, lr = lane & 7;
    int a_row_off = (lg & 1) * 8 + lr;
    int a_col_off = (lg >> 1) * 8;
    int b_row_off = (lg >> 1) * 8 + lr;
    int b_col_off = (lg & 1) * 8;

    uint32_t sbAh = smem_u32(&Ah[0][0]);
    uint32_t sbAl = smem_u32(&Al[0][0]);
    uint32_t sbBh = smem_u32(&Bh[0][0]);
    uint32_t sbBl = smem_u32(&Bl[0][0]);

    for (int kc = 0; kc < 2; kc++) {
#pragma unroll
        for (int it = 0; it < 2; it++) {
            int task = t + it * 256;          // 0..511
            int r = task >> 3, q = task & 7;  // row, 8-k chunk
            size_t goff = (size_t)(brow + r) * 128 + kc * 64 + q * 8;
            float4 v0 = __ldg((const float4*)(x + goff));
            float4 v1 = __ldg((const float4*)(x + goff + 4));
            __nv_bfloat16 h[8], l[8];
            split_bf(v0.x, h[0], l[0]); split_bf(v0.y, h[1], l[1]);
            split_bf(v0.z, h[2], l[2]); split_bf(v0.w, h[3], l[3]);
            split_bf(v1.x, h[4], l[4]); split_bf(v1.y, h[5], l[5]);
            split_bf(v1.z, h[6], l[6]); split_bf(v1.w, h[7], l[7]);
            uint4 hv = make_uint4(pack_bf2(h[0], h[1]), pack_bf2(h[2], h[3]),
                                  pack_bf2(h[4], h[5]), pack_bf2(h[6], h[7]));
            uint4 lv = make_uint4(pack_bf2(l[0], l[1]), pack_bf2(l[2], l[3]),
                                  pack_bf2(l[4], l[5]), pack_bf2(l[6], l[7]));
            *(uint4*)&Ah[r][q * 8] = hv;
            *(uint4*)&Al[r][q * 8] = lv;
            *(uint4*)(g_xhi + goff) = hv;
            *(uint4*)(g_xlo + goff) = lv;
        }
#pragma unroll
        for (int it = 0; it < 3; it++) {
            int task = t + it * 256;
            int n = task >> 3, q = task & 7;
            *(uint4*)&Bh[n][q * 8] = __ldg((const uint4*)(g_Ehi + n * 128 + kc * 64 + q * 8));
            *(uint4*)&Bl[n][q * 8] = __ldg((const uint4*)(g_Elo + n * 128 + kc * 64 + q * 8));
        }
        __syncthreads();

#pragma unroll
        for (int ks = 0; ks < 4; ks++) {
            uint32_t ah[4], al[4], bhi[6][2], blo[6][2];
#pragma unroll
            for (int np = 0; np < 3; np++) {
                uint32_t addr = sbBh +
                    ((warp_n * 40 + np * 16 + b_row_off) * EP + ks * 16 + b_col_off) * 2;
                LDSM_X4(bhi[np * 2][0], bhi[np * 2][1],
                        bhi[np * 2 + 1][0], bhi[np * 2 + 1][1], addr);
                addr = sbBl +
                    ((warp_n * 40 + np * 16 + b_row_off) * EP + ks * 16 + b_col_off) * 2;
                LDSM_X4(blo[np * 2][0], blo[np * 2][1],
                        blo[np * 2 + 1][0], blo[np * 2 + 1][1], addr);
            }
            {
                uint32_t addr = sbAh +
                    ((warp_m * 16 + a_row_off) * EP + ks * 16 + a_col_off) * 2;
                LDSM_X4(ah[0], ah[1], ah[2], ah[3], addr);
                addr = sbAl +
                    ((warp_m * 16 + a_row_off) * EP + ks * 16 + a_col_off) * 2;
                LDSM_X4(al[0], al[1], al[2], al[3], addr);
            }
#pragma unroll
            for (int ni = 0; ni < 5; ni++) {
                MMA16816(acc[ni], ah, bhi[ni]);
                MMA16816(acc[ni], ah, blo[ni]);
                MMA16816(acc[ni], al, bhi[ni]);
            }
        }
        __syncthreads();
    }

    int qrow = lane >> 2, qcol = (lane & 3) * 2;
    int row0 = brow + warp_m * 16 + qrow;
#pragma unroll
    for (int ni = 0; ni < 5; ni++) {
        int c = warp_n * 40 + ni * 8 + qcol;
        if (c < 64) {
            float2 b2 = *(const float2*)(bh + c);
            float2 v0 = make_float2(acc[ni][0] + b2.x, acc[ni][1] + b2.y);
            float2 v1 = make_float2(acc[ni][2] + b2.x, acc[ni][3] + b2.y);
            *(float2*)(g_h + (size_t)row0 * 64 + c)       = v0;
            *(float2*)(g_h + (size_t)(row0 + 8) * 64 + c) = v1;
        } else if (c < 68) {
            int sc = c - 64;
            float2 b2 = *(const float2*)(bs + sc);
            float2 v0 = make_float2(acc[ni][0] + b2.x, acc[ni][1] + b2.y);
            float2 v1 = make_float2(acc[ni][2] + b2.x, acc[ni][3] + b2.y);
            *(float2*)(g_s + (size_t)row0 * 4 + sc)       = v0;
            *(float2*)(g_s + (size_t)(row0 + 8) * 4 + sc) = v1;
        }
    }
}

// ============================================================
// Kernel 2: per-graph kNN + fused aggregation.
//   R10-proven logic; regrid (64,2)x512 -> (64,4)x256 so 256
//   CTAs cover all 148 SMs at 2 CTAs/SM (latency hiding for
//   both the scan and the gather phase).
// ============================================================
#define KNN_CHAIN(v) do { \
    float _v = (v); \
    _Pragma("unroll") \
    for (int _tt = 0; _tt < Kn; _tt++) { \
        float _lo = fminf(_v, lst[_tt]); \
        _v = fmaxf(_v, lst[_tt]); \
        lst[_tt] = _lo; \
    } } while (0)

#define KNN_FLUSH() do { \
    _Pragma("unroll") \
    for (int _k = 0; _k < 4; _k++) { \
        float _bv = (_k == 0) ? b0 : (_k == 1) ? b1 : (_k == 2) ? b2 : b3; \
        if (_k < cnt && _bv < lst[Kn - 1]) KNN_CHAIN(_bv); \
    } \
    cnt = 0; gate = lst[Kn - 1]; } while (0)

#define KNN_STEP(jj) do { \
    float4 mj = sm2[jj]; \
    float tv = fmaf(mj.x, si.x, snj[jj]); \
    tv = fmaf(mj.y, si.y, tv); \
    tv = fmaf(mj.z, si.z, tv); \
    tv = fmaf(mj.w, si.w, tv); \
    float pv = __uint_as_float((__float_as_uint(tv) & 0xFFFFFC00u) | (unsigned)(jj)); \
    if (pv < gate) { b3 = b2; b2 = b1; b1 = b0; b0 = pv; cnt++; } } while (0)

__global__ __launch_bounds__(256) void k_knn()
{
    __shared__ float4 sm2[Lg];   // -2 * s_j
    __shared__ float  snj[Lg];   // |s_j|^2
    int b = blockIdx.x;
    int base = b * Lg;

    for (int i = threadIdx.x; i < Lg; i += blockDim.x) {
        float4 s = *(const float4*)(g_s + (size_t)(base + i) * 4);
        sm2[i] = make_float4(-2.f * s.x, -2.f * s.y, -2.f * s.z, -2.f * s.w);
        snj[i] = s.x * s.x + s.y * s.y + s.z * s.z + s.w * s.w;
    }
    __syncthreads();

    int t = threadIdx.x;
    int lane = t & 31;
    int rloc = blockIdx.y * 256 + t;          // row within graph
    float4 m2i = sm2[rloc];
    float4 si = make_float4(-0.5f * m2i.x, -0.5f * m2i.y, -0.5f * m2i.z, -0.5f * m2i.w);
    float nrm = snj[rloc];

    float lst[Kn];
#pragma unroll
    for (int tt = 0; tt < Kn; tt++) lst[tt] = FLT_MAX;

    float b0 = 0.f, b1 = 0.f, b2 = 0.f, b3 = 0.f;
    int cnt = 0;
    float gate = FLT_MAX;

#pragma unroll 4
    for (int j = 0; j < Lg; j += 2) {
        KNN_STEP(j);
        KNN_STEP(j + 1);
        if (__any_sync(0xffffffffu, cnt >= 3)) KNN_FLUSH();
    }
    KNN_FLUSH();

    int   oid[Kn];
    float ow [Kn];
#pragma unroll
    for (int tt = 0; tt < Kn; tt++) {
        int j = (int)(__float_as_uint(lst[tt]) & 1023u);
        float4 mj = sm2[j];
        float tv = fmaf(mj.x, si.x, snj[j]);
        tv = fmaf(mj.y, si.y, tv);
        tv = fmaf(mj.z, si.z, tv);
        tv = fmaf(mj.w, si.w, tv);
        float d2 = fmaxf(nrm + tv, 0.f);
        oid[tt] = base + j;
        ow [tt] = __expf(-10.f * d2);
    }

    // ---- fused aggregation: warp handles its 32 rows ----
    int wrow0 = base + blockIdx.y * 256 + (t >> 5) * 32;
#pragma unroll 1
    for (int l = 0; l < 32; l++) {
        float s0 = 0.f, s1 = 0.f, m0 = -FLT_MAX, m1 = -FLT_MAX;
#pragma unroll
        for (int nb = 0; nb < Kn; nb++) {
            int   id = __shfl_sync(0xffffffffu, oid[nb], l);
            float wt = __shfl_sync(0xffffffffu, ow[nb], l);
            float v0 = __ldg(&g_h[(size_t)id * 64 + lane])      * wt;
            float v1 = __ldg(&g_h[(size_t)id * 64 + 32 + lane]) * wt;
            s0 += v0;  s1 += v1;
            m0 = fmaxf(m0, v0);  m1 = fmaxf(m1, v1);
        }
        size_t bidx = (size_t)(wrow0 + l) * 128;
        float vals[4] = { s0 * (1.f / 16.f), s1 * (1.f / 16.f), m0, m1 };
        int   cols[4] = { lane, 32 + lane, 64 + lane, 96 + lane };
#pragma unroll
        for (int q = 0; q < 4; q++) {
            __nv_bfloat16 h, lo;
            split_bf(vals[q], h, lo);
            g_ahi[bidx + cols[q]] = h;
            g_alo[bidx + cols[q]] = lo;
        }
    }
}

// ============================================================
// Kernel 4: out = relu([x|agg] @ W_out + b_out)
//   Double-buffered smem + cp.async staging (LDGSTS): staging
//   has no register-resident data, drains behind the MMAs.
// ============================================================
#define APITCH 40

__global__ __launch_bounds__(256) void k_out(
    const float* __restrict__ bout,
    float* __restrict__ out)
{
    __shared__ __nv_bfloat16 Ahi_s[2][128][APITCH];
    __shared__ __nv_bfloat16 Alo_s[2][128][APITCH];
    __shared__ __nv_bfloat16 Bhi_s[2][128][APITCH];
    __shared__ __nv_bfloat16 Blo_s[2][128][APITCH];

    int t = threadIdx.x;
    int wid = t >> 5, lane = t & 31;
    int warp_m = wid & 1;
    int warp_n = wid >> 1;
    int block_row = blockIdx.x * 128;

    float acc[4][4][4];
#pragma unroll
    for (int mi = 0; mi < 4; mi++)
#pragma unroll
        for (int ni = 0; ni < 4; ni++)
#pragma unroll
            for (int r = 0; r < 4; r++) acc[mi][ni][r] = 0.f;

    int lg = lane >> 3, lr = lane & 7;
    int a_row_off = (lg & 1) * 8 + lr;
    int a_col_off = (lg >> 1) * 8;
    int b_row_off = (lg >> 1) * 8 + lr;
    int b_col_off = (lg & 1) * 8;

    auto stage = [&](int kc, int buf) {
        const __nv_bfloat16* sh = ((kc < 4) ? g_xhi : g_ahi) + (kc & 3) * 32;
        const __nv_bfloat16* sl = ((kc < 4) ? g_xlo : g_alo) + (kc & 3) * 32;
#pragma unroll
        for (int it = 0; it < 2; it++) {
            int task = t + it * 256;
            int r = task >> 2, q = task & 3;
            size_t goff = (size_t)(block_row + r) * 128 + q * 8;
            __pipeline_memcpy_async(&Ahi_s[buf][r][q * 8], sh + goff, 16);
            __pipeline_memcpy_async(&Alo_s[buf][r][q * 8], sl + goff, 16);
        }
#pragma unroll
        for (int it = 0; it < 2; it++) {
            int task = t + it * 256;
            int n = task >> 2, q = task & 3;
            __pipeline_memcpy_async(&Bhi_s[buf][n][q * 8], g_Bhi + n * 256 + kc * 32 + q * 8, 16);
            __pipeline_memcpy_async(&Blo_s[buf][n][q * 8], g_Blo + n * 256 + kc * 32 + q * 8, 16);
        }
        __pipeline_commit();
    };

    stage(0, 0);
    __pipeline_wait_prior(0);
    __syncthreads();

    for (int kc = 0; kc < 8; kc++) {
        int cur = kc & 1;
        if (kc < 7) stage(kc + 1, cur ^ 1);   // async; drains behind MMAs

        uint32_t sbAhi = smem_u32(&Ahi_s[cur][0][0]);
        uint32_t sbAlo = smem_u32(&Alo_s[cur][0][0]);
        uint32_t sbBhi = smem_u32(&Bhi_s[cur][0][0]);
        uint32_t sbBlo = smem_u32(&Blo_s[cur][0][0]);

#pragma unroll
        for (int ks = 0; ks < 2; ks++) {
            uint32_t a[4][4], bhi[4][2], blo[4][2];
#pragma unroll
            for (int np = 0; np < 2; np++) {
                uint32_t addr = sbBhi +
                    ((warp_n * 32 + np * 16 + b_row_off) * APITCH + ks * 16 + b_col_off) * 2;
                LDSM_X4(bhi[np * 2][0], bhi[np * 2][1],
                        bhi[np * 2 + 1][0], bhi[np * 2 + 1][1], addr);
                addr = sbBlo +
                    ((warp_n * 32 + np * 16 + b_row_off) * APITCH + ks * 16 + b_col_off) * 2;
                LDSM_X4(blo[np * 2][0], blo[np * 2][1],
                        blo[np * 2 + 1][0], blo[np * 2 + 1][1], addr);
            }
#pragma unroll
            for (int mi = 0; mi < 4; mi++) {
                uint32_t addr = sbAhi +
                    ((warp_m * 64 + mi * 16 + a_row_off) * APITCH + ks * 16 + a_col_off) * 2;
                LDSM_X4(a[mi][0], a[mi][1], a[mi][2], a[mi][3], addr);
            }
#pragma unroll
            for (int mi = 0; mi < 4; mi++)
#pragma unroll
                for (int ni = 0; ni < 4; ni++) {
                    MMA16816(acc[mi][ni], a[mi], bhi[ni]);
                    MMA16816(acc[mi][ni], a[mi], blo[ni]);
                }
#pragma unroll
            for (int mi = 0; mi < 4; mi++) {
                uint32_t addr = sbAlo +
                    ((warp_m * 64 + mi * 16 + a_row_off) * APITCH + ks * 16 + a_col_off) * 2;
                LDSM_X4(a[mi][0], a[mi][1], a[mi][2], a[mi][3], addr);
            }
#pragma unroll
            for (int mi = 0; mi < 4; mi++)
#pragma unroll
                for (int ni = 0; ni < 4; ni++)
                    MMA16816(acc[mi][ni], a[mi], bhi[ni]);
        }
        if (kc < 7) __pipeline_wait_prior(0);
        __syncthreads();
    }

    int qrow = lane >> 2, qcol = (lane & 3) * 2;
    float2 bias2[4];
#pragma unroll
    for (int ni = 0; ni < 4; ni++)
        bias2[ni] = *(const float2*)(bout + warp_n * 32 + ni * 8 + qcol);

#pragma unroll
    for (int mi = 0; mi < 4; mi++) {
        int row0 = block_row + warp_m * 64 + mi * 16 + qrow;
#pragma unroll
        for (int ni = 0; ni < 4; ni++) {
            int col = warp_n * 32 + ni * 8 + qcol;
            float2 v0, v1;
            v0.x = fmaxf(acc[mi][ni][0] + bias2[ni].x, 0.f);
            v0.y = fmaxf(acc[mi][ni][1] + bias2[ni].y, 0.f);
            v1.x = fmaxf(acc[mi][ni][2] + bias2[ni].x, 0.f);
            v1.y = fmaxf(acc[mi][ni][3] + bias2[ni].y, 0.f);
            *(float2*)(out + (size_t)row0 * 128 + col)       = v0;
            *(float2*)(out + (size_t)(row0 + 8) * 128 + col) = v1;
        }
    }
}

// ============================================================
extern "C" void kernel_launch(void* const* d_in, const int* in_sizes, int n_in,
                              void* d_out, int out_size)
{
    const float* x    = (const float*)d_in[0];
    const float* Ws   = (const float*)d_in[1];
    const float* bs   = (const float*)d_in[2];
    const float* Wh   = (const float*)d_in[3];
    const float* bh   = (const float*)d_in[4];
    const float* Wout = (const float*)d_in[5];
    const float* bout = (const float*)d_in[6];
    float* out = (float*)d_out;

    k_wcvt<<<64, 512>>>(Wout, Ws, Wh);
    k_embed<<<Ntot / 64, 256>>>(x, bs, bh);
    k_knn<<<dim3(Bg, 4), 256>>>();
    k_out<<<Ntot / 128, 256>>>(bout, out);
}

// round 17
// speedup vs baseline: 1.0518x; 1.0518x over previous
#include <cuda_runtime.h>
#include <cuda_pipeline.h>
#include <cuda_bf16.h>
#include <cstdint>
#include <float.h>

#define Bg   64
#define Lg   1024
#define Kn   16
#define Ntot (Bg * Lg)

// ---- scratch (static device globals; zero-initialized; no allocation) ----
__device__ float g_s[Ntot * 4];             //  1 MB  learned kNN space
__device__ float g_h[Ntot * 64];            // 16 MB  propagated features (fp32)
__device__ __nv_bfloat16 g_xhi[Ntot * 128]; // 16 MB  x split hi   [node][k]
__device__ __nv_bfloat16 g_xlo[Ntot * 128]; // 16 MB  x split lo
__device__ __nv_bfloat16 g_ahi[Ntot * 128]; // 16 MB  agg split hi [node][mean|max]
__device__ __nv_bfloat16 g_alo[Ntot * 128]; // 16 MB  agg split lo
__device__ __nv_bfloat16 g_Bhi[128 * 256];  // W_out^T hi  [n][k=256]
__device__ __nv_bfloat16 g_Blo[128 * 256];  // W_out^T lo
__device__ __nv_bfloat16 g_Ehi[96 * 128];   // W_comb^T hi [n=96(pad)][k=128]
__device__ __nv_bfloat16 g_Elo[96 * 128];   // W_comb^T lo (rows 72..95 stay zero)

__device__ __forceinline__ uint32_t smem_u32(const void* p) {
    uint32_t a;
    asm("{ .reg .u64 t; cvta.to.shared.u64 t, %1; cvt.u32.u64 %0, t; }"
        : "=r"(a) : "l"(p));
    return a;
}

#define LDSM_X4(r0, r1, r2, r3, addr) \
    asm volatile("ldmatrix.sync.aligned.m8n8.x4.shared.b16 {%0,%1,%2,%3}, [%4];" \
                 : "=r"(r0), "=r"(r1), "=r"(r2), "=r"(r3) : "r"(addr))

#define MMA16816(c, a, b) \
    asm volatile("mma.sync.aligned.m16n8k16.row.col.f32.bf16.bf16.f32 " \
                 "{%0,%1,%2,%3}, {%4,%5,%6,%7}, {%8,%9}, {%0,%1,%2,%3};" \
                 : "+f"((c)[0]), "+f"((c)[1]), "+f"((c)[2]), "+f"((c)[3]) \
                 : "r"((a)[0]), "r"((a)[1]), "r"((a)[2]), "r"((a)[3]), \
                   "r"((b)[0]), "r"((b)[1]))

__device__ __forceinline__ unsigned pack_bf2(__nv_bfloat16 a, __nv_bfloat16 b) {
    __nv_bfloat162 p = __halves2bfloat162(a, b);
    return *reinterpret_cast<unsigned*>(&p);
}
__device__ __forceinline__ void split_bf(float v, __nv_bfloat16& h, __nv_bfloat16& l) {
    h = __float2bfloat16_rn(v);
    l = __float2bfloat16_rn(v - __bfloat162float(h));
}

// ============================================================
// Kernel 0: weight prep (R8 proven).
// ============================================================
__global__ __launch_bounds__(512) void k_wcvt(
    const float* __restrict__ Wout,
    const float* __restrict__ Ws, const float* __restrict__ Wh)
{
    int idx = blockIdx.x * 512 + threadIdx.x;      // 0..32767
    {
        int n = idx & 127, k = idx >> 7;
        float w = Wout[(size_t)k * 128 + n];
        __nv_bfloat16 h, l;
        split_bf(w, h, l);
        g_Bhi[n * 256 + k] = h;
        g_Blo[n * 256 + k] = l;
    }
    if (idx < 72 * 128) {
        int n = idx >> 7, k = idx & 127;
        float w = (n < 64) ? Wh[k * 64 + n] : Ws[k * 4 + (n - 64)];
        __nv_bfloat16 h, l;
        split_bf(w, h, l);
        g_Ehi[n * 128 + k] = h;
        g_Elo[n * 128 + k] = l;
    }
}

// ============================================================
// Kernel 1: fused s/h embedding via HMMA split-bf16 (R10 proven).
// ============================================================
#define EP 72

__global__ __launch_bounds__(256) void k_embed(
    const float* __restrict__ x,
    const float* __restrict__ bs, const float* __restrict__ bh)
{
    __shared__ __nv_bfloat16 Ah[64][EP];
    __shared__ __nv_bfloat16 Al[64][EP];
    __shared__ __nv_bfloat16 Bh[96][EP];
    __shared__ __nv_bfloat16 Bl[96][EP];

    int t = threadIdx.x;
    int wid = t >> 5, lane = t & 31;
    int warp_m = wid & 3;
    int warp_n = wid >> 2;
    int brow = blockIdx.x * 64;

    float acc[5][4];
#pragma unroll
    for (int ni = 0; ni < 5; ni++)
#pragma unroll
        for (int r = 0; r < 4; r++) acc[ni][r] = 0.f;

    int lg = lane >> 3, lr = lane & 7;
    int a_row_off = (lg & 1) * 8 + lr;
    int a_col_off = (lg >> 1) * 8;
    int b_row_off = (lg >> 1) * 8 + lr;
    int b_col_off = (lg & 1) * 8;

    uint32_t sbAh = smem_u32(&Ah[0][0]);
    uint32_t sbAl = smem_u32(&Al[0][0]);
    uint32_t sbBh = smem_u32(&Bh[0][0]);
    uint32_t sbBl = smem_u32(&Bl[0][0]);

    for (int kc = 0; kc < 2; kc++) {
#pragma unroll
        for (int it = 0; it < 2; it++) {
            int task = t + it * 256;          // 0..511
            int r = task >> 3, q = task & 7;  // row, 8-k chunk
            size_t goff = (size_t)(brow + r) * 128 + kc * 64 + q * 8;
            float4 v0 = __ldg((const float4*)(x + goff));
            float4 v1 = __ldg((const float4*)(x + goff + 4));
            __nv_bfloat16 h[8], l[8];
            split_bf(v0.x, h[0], l[0]); split_bf(v0.y, h[1], l[1]);
            split_bf(v0.z, h[2], l[2]); split_bf(v0.w, h[3], l[3]);
            split_bf(v1.x, h[4], l[4]); split_bf(v1.y, h[5], l[5]);
            split_bf(v1.z, h[6], l[6]); split_bf(v1.w, h[7], l[7]);
            uint4 hv = make_uint4(pack_bf2(h[0], h[1]), pack_bf2(h[2], h[3]),
                                  pack_bf2(h[4], h[5]), pack_bf2(h[6], h[7]));
            uint4 lv = make_uint4(pack_bf2(l[0], l[1]), pack_bf2(l[2], l[3]),
                                  pack_bf2(l[4], l[5]), pack_bf2(l[6], l[7]));
            *(uint4*)&Ah[r][q * 8] = hv;
            *(uint4*)&Al[r][q * 8] = lv;
            *(uint4*)(g_xhi + goff) = hv;
            *(uint4*)(g_xlo + goff) = lv;
        }
#pragma unroll
        for (int it = 0; it < 3; it++) {
            int task = t + it * 256;
            int n = task >> 3, q = task & 7;
            *(uint4*)&Bh[n][q * 8] = __ldg((const uint4*)(g_Ehi + n * 128 + kc * 64 + q * 8));
            *(uint4*)&Bl[n][q * 8] = __ldg((const uint4*)(g_Elo + n * 128 + kc * 64 + q * 8));
        }
        __syncthreads();

#pragma unroll
        for (int ks = 0; ks < 4; ks++) {
            uint32_t ah[4], al[4], bhi[6][2], blo[6][2];
#pragma unroll
            for (int np = 0; np < 3; np++) {
                uint32_t addr = sbBh +
                    ((warp_n * 40 + np * 16 + b_row_off) * EP + ks * 16 + b_col_off) * 2;
                LDSM_X4(bhi[np * 2][0], bhi[np * 2][1],
                        bhi[np * 2 + 1][0], bhi[np * 2 + 1][1], addr);
                addr = sbBl +
                    ((warp_n * 40 + np * 16 + b_row_off) * EP + ks * 16 + b_col_off) * 2;
                LDSM_X4(blo[np * 2][0], blo[np * 2][1],
                        blo[np * 2 + 1][0], blo[np * 2 + 1][1], addr);
            }
            {
                uint32_t addr = sbAh +
                    ((warp_m * 16 + a_row_off) * EP + ks * 16 + a_col_off) * 2;
                LDSM_X4(ah[0], ah[1], ah[2], ah[3], addr);
                addr = sbAl +
                    ((warp_m * 16 + a_row_off) * EP + ks * 16 + a_col_off) * 2;
                LDSM_X4(al[0], al[1], al[2], al[3], addr);
            }
#pragma unroll
            for (int ni = 0; ni < 5; ni++) {
                MMA16816(acc[ni], ah, bhi[ni]);
                MMA16816(acc[ni], ah, blo[ni]);
                MMA16816(acc[ni], al, bhi[ni]);
            }
        }
        __syncthreads();
    }

    int qrow = lane >> 2, qcol = (lane & 3) * 2;
    int row0 = brow + warp_m * 16 + qrow;
#pragma unroll
    for (int ni = 0; ni < 5; ni++) {
        int c = warp_n * 40 + ni * 8 + qcol;
        if (c < 64) {
            float2 b2 = *(const float2*)(bh + c);
            float2 v0 = make_float2(acc[ni][0] + b2.x, acc[ni][1] + b2.y);
            float2 v1 = make_float2(acc[ni][2] + b2.x, acc[ni][3] + b2.y);
            *(float2*)(g_h + (size_t)row0 * 64 + c)       = v0;
            *(float2*)(g_h + (size_t)(row0 + 8) * 64 + c) = v1;
        } else if (c < 68) {
            int sc = c - 64;
            float2 b2 = *(const float2*)(bs + sc);
            float2 v0 = make_float2(acc[ni][0] + b2.x, acc[ni][1] + b2.y);
            float2 v1 = make_float2(acc[ni][2] + b2.x, acc[ni][3] + b2.y);
            *(float2*)(g_s + (size_t)row0 * 4 + sc)       = v0;
            *(float2*)(g_s + (size_t)(row0 + 8) * 4 + sc) = v1;
        }
    }
}

// ============================================================
// Kernel 2: per-graph kNN + fused aggregation (R15 proven:
//   (Bg,2) x 512 threads).
// ============================================================
#define KNN_CHAIN(v) do { \
    float _v = (v); \
    _Pragma("unroll") \
    for (int _tt = 0; _tt < Kn; _tt++) { \
        float _lo = fminf(_v, lst[_tt]); \
        _v = fmaxf(_v, lst[_tt]); \
        lst[_tt] = _lo; \
    } } while (0)

#define KNN_FLUSH() do { \
    _Pragma("unroll") \
    for (int _k = 0; _k < 4; _k++) { \
        float _bv = (_k == 0) ? b0 : (_k == 1) ? b1 : (_k == 2) ? b2 : b3; \
        if (_k < cnt && _bv < lst[Kn - 1]) KNN_CHAIN(_bv); \
    } \
    cnt = 0; gate = lst[Kn - 1]; } while (0)

#define KNN_STEP(jj) do { \
    float4 mj = sm2[jj]; \
    float tv = fmaf(mj.x, si.x, snj[jj]); \
    tv = fmaf(mj.y, si.y, tv); \
    tv = fmaf(mj.z, si.z, tv); \
    tv = fmaf(mj.w, si.w, tv); \
    float pv = __uint_as_float((__float_as_uint(tv) & 0xFFFFFC00u) | (unsigned)(jj)); \
    if (pv < gate) { b3 = b2; b2 = b1; b1 = b0; b0 = pv; cnt++; } } while (0)

__global__ __launch_bounds__(512) void k_knn()
{
    __shared__ float4 sm2[Lg];   // -2 * s_j
    __shared__ float  snj[Lg];   // |s_j|^2
    int b = blockIdx.x;
    int base = b * Lg;

    for (int i = threadIdx.x; i < Lg; i += blockDim.x) {
        float4 s = *(const float4*)(g_s + (size_t)(base + i) * 4);
        sm2[i] = make_float4(-2.f * s.x, -2.f * s.y, -2.f * s.z, -2.f * s.w);
        snj[i] = s.x * s.x + s.y * s.y + s.z * s.z + s.w * s.w;
    }
    __syncthreads();

    int t = threadIdx.x;
    int lane = t & 31;
    int rloc = blockIdx.y * 512 + t;          // row within graph
    float4 m2i = sm2[rloc];
    float4 si = make_float4(-0.5f * m2i.x, -0.5f * m2i.y, -0.5f * m2i.z, -0.5f * m2i.w);
    float nrm = snj[rloc];

    float lst[Kn];
#pragma unroll
    for (int tt = 0; tt < Kn; tt++) lst[tt] = FLT_MAX;

    float b0 = 0.f, b1 = 0.f, b2 = 0.f, b3 = 0.f;
    int cnt = 0;
    float gate = FLT_MAX;

#pragma unroll 4
    for (int j = 0; j < Lg; j += 2) {
        KNN_STEP(j);
        KNN_STEP(j + 1);
        if (__any_sync(0xffffffffu, cnt >= 3)) KNN_FLUSH();
    }
    KNN_FLUSH();

    int   oid[Kn];
    float ow [Kn];
#pragma unroll
    for (int tt = 0; tt < Kn; tt++) {
        int j = (int)(__float_as_uint(lst[tt]) & 1023u);
        float4 mj = sm2[j];
        float tv = fmaf(mj.x, si.x, snj[j]);
        tv = fmaf(mj.y, si.y, tv);
        tv = fmaf(mj.z, si.z, tv);
        tv = fmaf(mj.w, si.w, tv);
        float d2 = fmaxf(nrm + tv, 0.f);
        oid[tt] = base + j;
        ow [tt] = __expf(-10.f * d2);
    }

    // ---- fused aggregation: warp handles its 32 rows ----
    int wrow0 = base + blockIdx.y * 512 + (t >> 5) * 32;
#pragma unroll 1
    for (int l = 0; l < 32; l++) {
        float s0 = 0.f, s1 = 0.f, m0 = -FLT_MAX, m1 = -FLT_MAX;
#pragma unroll
        for (int nb = 0; nb < Kn; nb++) {
            int   id = __shfl_sync(0xffffffffu, oid[nb], l);
            float wt = __shfl_sync(0xffffffffu, ow[nb], l);
            float v0 = __ldg(&g_h[(size_t)id * 64 + lane])      * wt;
            float v1 = __ldg(&g_h[(size_t)id * 64 + 32 + lane]) * wt;
            s0 += v0;  s1 += v1;
            m0 = fmaxf(m0, v0);  m1 = fmaxf(m1, v1);
        }
        size_t bidx = (size_t)(wrow0 + l) * 128;
        float vals[4] = { s0 * (1.f / 16.f), s1 * (1.f / 16.f), m0, m1 };
        int   cols[4] = { lane, 32 + lane, 64 + lane, 96 + lane };
#pragma unroll
        for (int q = 0; q < 4; q++) {
            __nv_bfloat16 h, lo;
            split_bf(vals[q], h, lo);
            g_ahi[bidx + cols[q]] = h;
            g_alo[bidx + cols[q]] = lo;
        }
    }
}

// ============================================================
// Kernel 4: out = relu([x|agg] @ W_out + b_out)
//   Double-buffered smem + cp.async staging (R16 proven, 49.1us).
// ============================================================
#define APITCH 40

__global__ __launch_bounds__(256) void k_out(
    const float* __restrict__ bout,
    float* __restrict__ out)
{
    __shared__ __nv_bfloat16 Ahi_s[2][128][APITCH];
    __shared__ __nv_bfloat16 Alo_s[2][128][APITCH];
    __shared__ __nv_bfloat16 Bhi_s[2][128][APITCH];
    __shared__ __nv_bfloat16 Blo_s[2][128][APITCH];

    int t = threadIdx.x;
    int wid = t >> 5, lane = t & 31;
    int warp_m = wid & 1;
    int warp_n = wid >> 1;
    int block_row = blockIdx.x * 128;

    float acc[4][4][4];
#pragma unroll
    for (int mi = 0; mi < 4; mi++)
#pragma unroll
        for (int ni = 0; ni < 4; ni++)
#pragma unroll
            for (int r = 0; r < 4; r++) acc[mi][ni][r] = 0.f;

    int lg = lane >> 3, lr = lane & 7;
    int a_row_off = (lg & 1) * 8 + lr;
    int a_col_off = (lg >> 1) * 8;
    int b_row_off = (lg >> 1) * 8 + lr;
    int b_col_off = (lg & 1) * 8;

    auto stage = [&](int kc, int buf) {
        const __nv_bfloat16* sh = ((kc < 4) ? g_xhi : g_ahi) + (kc & 3) * 32;
        const __nv_bfloat16* sl = ((kc < 4) ? g_xlo : g_alo) + (kc & 3) * 32;
#pragma unroll
        for (int it = 0; it < 2; it++) {
            int task = t + it * 256;
            int r = task >> 2, q = task & 3;
            size_t goff = (size_t)(block_row + r) * 128 + q * 8;
            __pipeline_memcpy_async(&Ahi_s[buf][r][q * 8], sh + goff, 16);
            __pipeline_memcpy_async(&Alo_s[buf][r][q * 8], sl + goff, 16);
        }
#pragma unroll
        for (int it = 0; it < 2; it++) {
            int task = t + it * 256;
            int n = task >> 2, q = task & 3;
            __pipeline_memcpy_async(&Bhi_s[buf][n][q * 8], g_Bhi + n * 256 + kc * 32 + q * 8, 16);
            __pipeline_memcpy_async(&Blo_s[buf][n][q * 8], g_Blo + n * 256 + kc * 32 + q * 8, 16);
        }
        __pipeline_commit();
    };

    stage(0, 0);
    __pipeline_wait_prior(0);
    __syncthreads();

    for (int kc = 0; kc < 8; kc++) {
        int cur = kc & 1;
        if (kc < 7) stage(kc + 1, cur ^ 1);   // async; drains behind MMAs

        uint32_t sbAhi = smem_u32(&Ahi_s[cur][0][0]);
        uint32_t sbAlo = smem_u32(&Alo_s[cur][0][0]);
        uint32_t sbBhi = smem_u32(&Bhi_s[cur][0][0]);
        uint32_t sbBlo = smem_u32(&Blo_s[cur][0][0]);

#pragma unroll
        for (int ks = 0; ks < 2; ks++) {
            uint32_t a[4][4], bhi[4][2], blo[4][2];
#pragma unroll
            for (int np = 0; np < 2; np++) {
                uint32_t addr = sbBhi +
                    ((warp_n * 32 + np * 16 + b_row_off) * APITCH + ks * 16 + b_col_off) * 2;
                LDSM_X4(bhi[np * 2][0], bhi[np * 2][1],
                        bhi[np * 2 + 1][0], bhi[np * 2 + 1][1], addr);
                addr = sbBlo +
                    ((warp_n * 32 + np * 16 + b_row_off) * APITCH + ks * 16 + b_col_off) * 2;
                LDSM_X4(blo[np * 2][0], blo[np * 2][1],
                        blo[np * 2 + 1][0], blo[np * 2 + 1][1], addr);
            }
#pragma unroll
            for (int mi = 0; mi < 4; mi++) {
                uint32_t addr = sbAhi +
                    ((warp_m * 64 + mi * 16 + a_row_off) * APITCH + ks * 16 + a_col_off) * 2;
                LDSM_X4(a[mi][0], a[mi][1], a[mi][2], a[mi][3], addr);
            }
#pragma unroll
            for (int mi = 0; mi < 4; mi++)
#pragma unroll
                for (int ni = 0; ni < 4; ni++) {
                    MMA16816(acc[mi][ni], a[mi], bhi[ni]);
                    MMA16816(acc[mi][ni], a[mi], blo[ni]);
                }
#pragma unroll
            for (int mi = 0; mi < 4; mi++) {
                uint32_t addr = sbAlo +
                    ((warp_m * 64 + mi * 16 + a_row_off) * APITCH + ks * 16 + a_col_off) * 2;
                LDSM_X4(a[mi][0], a[mi][1], a[mi][2], a[mi][3], addr);
            }
#pragma unroll
            for (int mi = 0; mi < 4; mi++)
#pragma unroll
                for (int ni = 0; ni < 4; ni++)
                    MMA16816(acc[mi][ni], a[mi], bhi[ni]);
        }
        if (kc < 7) __pipeline_wait_prior(0);
        __syncthreads();
    }

    int qrow = lane >> 2, qcol = (lane & 3) * 2;
    float2 bias2[4];
#pragma unroll
    for (int ni = 0; ni < 4; ni++)
        bias2[ni] = *(const float2*)(bout + warp_n * 32 + ni * 8 + qcol);

#pragma unroll
    for (int mi = 0; mi < 4; mi++) {
        int row0 = block_row + warp_m * 64 + mi * 16 + qrow;
#pragma unroll
        for (int ni = 0; ni < 4; ni++) {
            int col = warp_n * 32 + ni * 8 + qcol;
            float2 v0, v1;
            v0.x = fmaxf(acc[mi][ni][0] + bias2[ni].x, 0.f);
            v0.y = fmaxf(acc[mi][ni][1] + bias2[ni].y, 0.f);
            v1.x = fmaxf(acc[mi][ni][2] + bias2[ni].x, 0.f);
            v1.y = fmaxf(acc[mi][ni][3] + bias2[ni].y, 0.f);
            *(float2*)(out + (size_t)row0 * 128 + col)       = v0;
            *(float2*)(out + (size_t)(row0 + 8) * 128 + col) = v1;
        }
    }
}

// ============================================================
extern "C" void kernel_launch(void* const* d_in, const int* in_sizes, int n_in,
                              void* d_out, int out_size)
{
    const float* x    = (const float*)d_in[0];
    const float* Ws   = (const float*)d_in[1];
    const float* bs   = (const float*)d_in[2];
    const float* Wh   = (const float*)d_in[3];
    const float* bh   = (const float*)d_in[4];
    const float* Wout = (const float*)d_in[5];
    const float* bout = (const float*)d_in[6];
    float* out = (float*)d_out;

    k_wcvt<<<64, 512>>>(Wout, Ws, Wh);
    k_embed<<<Ntot / 64, 256>>>(x, bs, bh);
    k_knn<<<dim3(Bg, 2), 512>>>();
    k_out<<<Ntot / 128, 256>>>(bout, out);
}